// round 13
// baseline (speedup 1.0000x reference)
#include <cuda_runtime.h>

#define Bsz 8
#define Lsz 1024
#define Dsz 512
#define HDsz 64
#define NCsz 128
#define Msz (Bsz*Lsz)
#define OUTHALF ((size_t)Msz*Dsz)
#define NEG_INF (-__int_as_float(0x7f800000))

__device__ float g_qr[Msz*Dsz], g_qi[Msz*Dsz];
__device__ float g_kr[Msz*Dsz], g_ki[Msz*Dsz];
__device__ float g_vr[Msz*Dsz], g_vi[Msz*Dsz];
__device__ float g_ar[Msz*Dsz], g_ai[Msz*Dsz];
__device__ float g_pr[Msz*Dsz], g_pi[Msz*Dsz];
__device__ int   g_idx[Msz];
__device__ float g_stk[Msz*Dsz];
__device__ float g_cn2[NCsz], g_gp[NCsz], g_go[NCsz];
__device__ double g_loss;

__device__ __forceinline__ void mma_tf32(float* c, const unsigned* a, const unsigned* b){
    asm volatile("mma.sync.aligned.m16n8k8.row.col.f32.tf32.tf32.f32 "
        "{%0,%1,%2,%3}, {%4,%5,%6,%7}, {%8,%9}, {%0,%1,%2,%3};"
        : "+f"(c[0]),"+f"(c[1]),"+f"(c[2]),"+f"(c[3])
        : "r"(a[0]),"r"(a[1]),"r"(a[2]),"r"(a[3]),"r"(b[0]),"r"(b[1]));
}
__device__ __forceinline__ unsigned su32(const void* p){
    return (unsigned)__cvta_generic_to_shared(p);
}
#define LDSM4(r,a) asm volatile("ldmatrix.sync.aligned.m8n8.x4.shared.b16 {%0,%1,%2,%3}, [%4];" \
    : "=r"((r)[0]),"=r"((r)[1]),"=r"((r)[2]),"=r"((r)[3]) : "r"(a))
#define CPA16(dst,src) asm volatile("cp.async.cg.shared.global [%0], [%1], 16;" :: "r"(su32(dst)), "l"(src))
#define CPA_COMMIT()   asm volatile("cp.async.commit_group;" ::: "memory")
#define CPA_WAIT0()    asm volatile("cp.async.wait_group 0;" ::: "memory")
#define CPA_WAIT1()    asm volatile("cp.async.wait_group 1;" ::: "memory")

#define AS_STRIDE (128*36)
#define BS_STRIDE (32*132)
#define BS_BASE   (2*AS_STRIDE)
#define GEMM_SMEM ((2*AS_STRIDE+2*BS_STRIDE)*4)

// ---------- prep ----------
__global__ void prep_kernel(const float* __restrict__ cb,
                            const float* __restrict__ gw,
                            const float* __restrict__ gb) {
    __shared__ float sh[3][4];
    const int j=blockIdx.x, t=threadIdx.x;
    if(j==0&&t==0) g_loss=0.0;
    float s2=0.f,d0=0.f,d1=0.f;
    for(int d=t; d<Dsz; d+=128){
        float c=cb[j*Dsz+d];
        s2+=c*c; d0+=c*gw[2*d]; d1+=c*gw[2*d+1];
    }
#pragma unroll
    for(int o=16;o;o>>=1){
        s2+=__shfl_xor_sync(0xffffffffu,s2,o);
        d0+=__shfl_xor_sync(0xffffffffu,d0,o);
        d1+=__shfl_xor_sync(0xffffffffu,d1,o);
    }
    if((t&31)==0){ sh[0][t>>5]=s2; sh[1][t>>5]=d0; sh[2][t>>5]=d1; }
    __syncthreads();
    if(t==0){
        float a=sh[0][0]+sh[0][1]+sh[0][2]+sh[0][3];
        float b=sh[1][0]+sh[1][1]+sh[1][2]+sh[1][3];
        float c=sh[2][0]+sh[2][1]+sh[2][2]+sh[2][3];
        g_cn2[j]=a;
        g_gp[j]=1.f/(1.f+expf(-(b+gb[0])));
        g_go[j]=1.f/(1.f+expf(-(c+gb[1])));
    }
}

// ---------- tf32 projection GEMM: cp.async 2-stage, fused gather ----------
__global__ __launch_bounds__(256) void proj_kernel(
        const int* __restrict__ tokens, const float* __restrict__ embed,
        const float* __restrict__ qw, const float* __restrict__ qb,
        const float* __restrict__ kw, const float* __restrict__ kb,
        const float* __restrict__ vw, const float* __restrict__ vb) {
    extern __shared__ unsigned smg[];
    const int z = blockIdx.z, pair = z>>1, im = z&1;
    const float* W; const float* bias; float* C;
    if (pair==0){W=qw;bias=qb;C=im?g_qi:g_qr;}
    else if (pair==1){W=kw;bias=kb;C=im?g_ki:g_kr;}
    else {W=vw;bias=vb;C=im?g_vi:g_vr;}
    W += (size_t)im*Dsz*Dsz;
    const float sgn = im?1.f:-1.f;
    const int m0=blockIdx.y*128, n0=blockIdx.x*128;
    const int tid=threadIdx.x, warp=tid>>5, lane=tid&31;
    const int wm=warp>>2, wn=warp&3, grp=lane>>2, tg=lane&3;
    const int lrow=lane&15, lcol=(lane&16)?4:0;
    const int arow=tid>>3, ac4=(tid&7)*4;
    const int brow=tid>>5, bc4=(tid&31)*4;
    size_t aoff[4];
#pragma unroll
    for(int u=0;u<4;u++)
        aoff[u]=(size_t)tokens[m0+arow+u*32]*Dsz;
    float acc[4][4][4];
#pragma unroll
    for(int i=0;i<4;i++)
#pragma unroll
        for(int j=0;j<4;j++)
#pragma unroll
            for(int k=0;k<4;k++) acc[i][j][k]=0.f;
#pragma unroll
    for(int u=0;u<4;u++){
        CPA16(&smg[(size_t)(arow+u*32)*36+ac4], embed+aoff[u]+ac4);
        CPA16(&smg[BS_BASE+(size_t)(brow+u*8)*132+bc4], W+(size_t)(brow+u*8)*Dsz+n0+bc4);
    }
    CPA_COMMIT();
    const int NCHUNK=Dsz/32;
    for(int c=0;c<NCHUNK;c++){
        if(c+1<NCHUNK){
            const int st=(c+1)&1, kn=(c+1)*32;
            unsigned* dA=smg+(size_t)st*AS_STRIDE;
            unsigned* dB=smg+BS_BASE+(size_t)st*BS_STRIDE;
#pragma unroll
            for(int u=0;u<4;u++){
                CPA16(&dA[(size_t)(arow+u*32)*36+ac4], embed+aoff[u]+kn+ac4);
                CPA16(&dB[(size_t)(brow+u*8)*132+bc4], W+(size_t)(kn+brow+u*8)*Dsz+n0+bc4);
            }
            CPA_COMMIT();
            CPA_WAIT1();
        } else CPA_WAIT0();
        __syncthreads();
        unsigned* As=smg+(size_t)(c&1)*AS_STRIDE;
        unsigned* Bs=smg+BS_BASE+(size_t)(c&1)*BS_STRIDE;
#pragma unroll
        for(int k8=0;k8<4;k8++){
            const int kb8=k8*8;
            unsigned af[4][4], bf[4][2];
#pragma unroll
            for(int mt=0;mt<4;mt++)
                LDSM4(af[mt], su32(&As[(size_t)(wm*64+mt*16+lrow)*36+kb8+lcol]));
#pragma unroll
            for(int nt=0;nt<4;nt++){
                int cix=wn*32+nt*8+grp;
                bf[nt][0]=Bs[(size_t)(kb8+tg)*132+cix]; bf[nt][1]=Bs[(size_t)(kb8+tg+4)*132+cix];
            }
#pragma unroll
            for(int mt=0;mt<4;mt++)
#pragma unroll
                for(int nt=0;nt<4;nt++) mma_tf32(acc[mt][nt],af[mt],bf[nt]);
        }
        __syncthreads();
    }
#pragma unroll
    for(int mt=0;mt<4;mt++){
#pragma unroll
        for(int nt=0;nt<4;nt++){
            int r=m0+wm*64+mt*16+grp;
            int cix=n0+wn*32+nt*8+2*tg;
            float b0=bias[cix]+sgn*bias[Dsz+cix];
            float b1=bias[cix+1]+sgn*bias[Dsz+cix+1];
            *(float2*)(C+(size_t)r*Dsz+cix)    =make_float2(acc[mt][nt][0]+b0,acc[mt][nt][1]+b1);
            *(float2*)(C+(size_t)(r+8)*Dsz+cix)=make_float2(acc[mt][nt][2]+b0,acc[mt][nt][3]+b1);
        }
    }
}

// ---------- tf32 fused complex O-projection: cp.async 2-stage, 3 CTA/SM target ----------
__global__ __launch_bounds__(256,3) void oproj_kernel(const float* __restrict__ ow,
                                                      const float* __restrict__ ob) {
    extern __shared__ unsigned smg[];
    const float* w0=ow; const float* w1=ow+(size_t)Dsz*Dsz;
    const int m0=blockIdx.y*128, n0=blockIdx.x*128;
    const bool isI = (n0>=Dsz);
    const int nloc = isI ? n0-Dsz : n0;
    const int tid=threadIdx.x, warp=tid>>5, lane=tid&31;
    const int wm=warp>>2, wn=warp&3, grp=lane>>2, tg=lane&3;
    const int lrow=lane&15, lcol=(lane&16)?4:0;
    const int arow=tid>>3, ac4=(tid&7)*4;
    const int brow=tid>>5, bc4=(tid&31)*4;
    float acc[4][4][4];
#pragma unroll
    for(int i=0;i<4;i++)
#pragma unroll
        for(int j=0;j<4;j++)
#pragma unroll
            for(int k=0;k<4;k++) acc[i][j][k]=0.f;
    const int NCHUNK=2*Dsz/32;
#pragma unroll
    for(int u=0;u<4;u++){
        const float* wsrc = isI ? w1 : w0;
        CPA16(&smg[(size_t)(arow+u*32)*36+ac4], g_ar+(size_t)(m0+arow+u*32)*Dsz+ac4);
        CPA16(&smg[BS_BASE+(size_t)(brow+u*8)*132+bc4], wsrc+(size_t)(brow+u*8)*Dsz+nloc+bc4);
    }
    CPA_COMMIT();
    for(int c=0;c<NCHUNK;c++){
        if(c+1<NCHUNK){
            const int st=(c+1)&1, kn=(c+1)*32;
            const bool khi=(kn>=Dsz);
            const float* asrc = khi ? g_ai : g_ar;
            const int akk = khi ? kn-Dsz : kn;
            const float* wsrc = isI ? (khi ? w0 : w1) : (khi ? w1 : w0);
            const int bkk = khi ? kn-Dsz : kn;
            unsigned* dA=smg+(size_t)st*AS_STRIDE;
            unsigned* dB=smg+BS_BASE+(size_t)st*BS_STRIDE;
#pragma unroll
            for(int u=0;u<4;u++){
                CPA16(&dA[(size_t)(arow+u*32)*36+ac4], asrc+(size_t)(m0+arow+u*32)*Dsz+akk+ac4);
                CPA16(&dB[(size_t)(brow+u*8)*132+bc4], wsrc+(size_t)(bkk+brow+u*8)*Dsz+nloc+bc4);
            }
            CPA_COMMIT();
            CPA_WAIT1();
        } else CPA_WAIT0();
        __syncthreads();
        const bool negA = (!isI) && (c>=NCHUNK/2);
        unsigned* As=smg+(size_t)(c&1)*AS_STRIDE;
        unsigned* Bs=smg+BS_BASE+(size_t)(c&1)*BS_STRIDE;
#pragma unroll
        for(int k8=0;k8<4;k8++){
            const int kb8=k8*8;
            unsigned af[4][4], bf[4][2];
#pragma unroll
            for(int mt=0;mt<4;mt++){
                LDSM4(af[mt], su32(&As[(size_t)(wm*64+mt*16+lrow)*36+kb8+lcol]));
                if(negA){
                    af[mt][0]^=0x80000000u; af[mt][1]^=0x80000000u;
                    af[mt][2]^=0x80000000u; af[mt][3]^=0x80000000u;
                }
            }
#pragma unroll
            for(int nt=0;nt<4;nt++){
                int cix=wn*32+nt*8+grp;
                bf[nt][0]=Bs[(size_t)(kb8+tg)*132+cix]; bf[nt][1]=Bs[(size_t)(kb8+tg+4)*132+cix];
            }
#pragma unroll
            for(int mt=0;mt<4;mt++)
#pragma unroll
                for(int nt=0;nt<4;nt++) mma_tf32(acc[mt][nt],af[mt],bf[nt]);
        }
        __syncthreads();
    }
    float* Cdst = isI ? g_pi : g_pr;
    const float s2 = isI ? 1.f : -1.f;
#pragma unroll
    for(int mt=0;mt<4;mt++){
#pragma unroll
        for(int nt=0;nt<4;nt++){
            int r=m0+wm*64+mt*16+grp;
            int cl=wn*32+nt*8+2*tg;
            int cg=nloc+cl;
            float b0=ob[cg]+s2*ob[Dsz+cg];
            float b1=ob[cg+1]+s2*ob[Dsz+cg+1];
            *(float2*)(Cdst+(size_t)r*Dsz+cg)    =make_float2(acc[mt][nt][0]+b0,acc[mt][nt][1]+b1);
            *(float2*)(Cdst+(size_t)(r+8)*Dsz+cg)=make_float2(acc[mt][nt][2]+b0,acc[mt][nt][3]+b1);
        }
    }
}

// ---------- tf32 flash attention v4 ----------
#define WAP 68
#define ATTN_SMEM (6*64*WAP*4)
__global__ __launch_bounds__(128) void attn_kernel() {
    extern __shared__ float smf[];
    float* sQr=smf;             float* sQi=sQr+64*WAP;
    float* sKr=sQi+64*WAP;      float* sKi=sKr+64*WAP;
    float* sVr=sKi+64*WAP;      float* sVi=sVr+64*WAP;
    const int bh=blockIdx.y, b=bh>>3, h=bh&7;
    const int bx=blockIdx.x, i0=bx*64;
    const int tid=threadIdx.x, warp=tid>>5, lane=tid&31;
    const int grp=lane>>2, tg=lane&3;
    const int lrow=lane&15, lcol=(lane&16)?4:0;
    const int krow=((lane>>4)<<3)|(lane&7), kcol=((lane>>3)&1)*4;
    const int wrow=warp*16;
    const size_t base=(size_t)b*Lsz*Dsz + h*HDsz;
#pragma unroll
    for(int u=0;u<8;u++){
        int li=tid+u*128, r=li>>4, c4=(li&15)*4;
        size_t g=base+(size_t)(i0+r)*Dsz+c4;
        CPA16(&sQr[r*WAP+c4], g_qr+g);
        CPA16(&sQi[r*WAP+c4], g_qi+g);
    }
    CPA_COMMIT();
    const int ntile=bx+1;
#pragma unroll
    for(int u=0;u<8;u++){
        int li=tid+u*128, r=li>>4, c4=(li&15)*4;
        size_t g=base+(size_t)r*Dsz+c4;
        CPA16(&sKr[r*WAP+c4], g_kr+g); CPA16(&sKi[r*WAP+c4], g_ki+g);
        CPA16(&sVr[r*WAP+c4], g_vr+g); CPA16(&sVi[r*WAP+c4], g_vi+g);
    }
    CPA_COMMIT();
    float m_run[2]={NEG_INF,NEG_INF}, l_run[2]={0.f,0.f};
    float accR[8][4], accI[8][4];
#pragma unroll
    for(int nt=0;nt<8;nt++)
#pragma unroll
        for(int k=0;k<4;k++){accR[nt][k]=0.f;accI[nt][k]=0.f;}
    const int srcA=(lane&~3)|(tg>>1), srcB=srcA|2;
    const bool odd=tg&1;
    for(int jt=0;jt<ntile;jt++){
        CPA_WAIT0();
        __syncthreads();
        const int s0=jt*64;
        float s_[8][4];
#pragma unroll
        for(int nt=0;nt<8;nt++)
#pragma unroll
            for(int k=0;k<4;k++) s_[nt][k]=0.f;
#pragma unroll
        for(int kc=0;kc<8;kc++){
            const int kb=kc*8;
            unsigned aR[4],aI[4];
            LDSM4(aR, su32(&sQr[(wrow+lrow)*WAP+kb+lcol]));
            LDSM4(aI, su32(&sQi[(wrow+lrow)*WAP+kb+lcol]));
#pragma unroll
            for(int ntp=0;ntp<4;ntp++){
                unsigned kR[4],kI[4];
                LDSM4(kR, su32(&sKr[(16*ntp+krow)*WAP+kb+kcol]));
                LDSM4(kI, su32(&sKi[(16*ntp+krow)*WAP+kb+kcol]));
                mma_tf32(s_[2*ntp],  aR,&kR[0]); mma_tf32(s_[2*ntp],  aI,&kI[0]);
                mma_tf32(s_[2*ntp+1],aR,&kR[2]); mma_tf32(s_[2*ntp+1],aI,&kI[2]);
            }
        }
        const bool diag=(jt==bx);
        const int r0=i0+wrow+grp, r1=r0+8;
#pragma unroll
        for(int nt=0;nt<8;nt++){
            const int c0=s0+nt*8+2*tg, c1=c0+1;
            s_[nt][0]*=0.125f; s_[nt][1]*=0.125f; s_[nt][2]*=0.125f; s_[nt][3]*=0.125f;
            if(diag){
                if(c0>r0)s_[nt][0]=NEG_INF; if(c1>r0)s_[nt][1]=NEG_INF;
                if(c0>r1)s_[nt][2]=NEG_INF; if(c1>r1)s_[nt][3]=NEG_INF;
            }
        }
        float mx0=NEG_INF, mx1=NEG_INF;
#pragma unroll
        for(int nt=0;nt<8;nt++){
            mx0=fmaxf(mx0,fmaxf(s_[nt][0],s_[nt][1]));
            mx1=fmaxf(mx1,fmaxf(s_[nt][2],s_[nt][3]));
        }
        mx0=fmaxf(mx0,__shfl_xor_sync(0xffffffffu,mx0,1));
        mx0=fmaxf(mx0,__shfl_xor_sync(0xffffffffu,mx0,2));
        mx1=fmaxf(mx1,__shfl_xor_sync(0xffffffffu,mx1,1));
        mx1=fmaxf(mx1,__shfl_xor_sync(0xffffffffu,mx1,2));
        const float mn0=fmaxf(m_run[0],mx0), mn1=fmaxf(m_run[1],mx1);
        const float al0=__expf(m_run[0]-mn0), al1=__expf(m_run[1]-mn1);
        m_run[0]=mn0; m_run[1]=mn1;
        float rs0=0.f, rs1=0.f;
#pragma unroll
        for(int nt=0;nt<8;nt++){
            s_[nt][0]=__expf(s_[nt][0]-mn0); s_[nt][1]=__expf(s_[nt][1]-mn0);
            s_[nt][2]=__expf(s_[nt][2]-mn1); s_[nt][3]=__expf(s_[nt][3]-mn1);
            rs0+=s_[nt][0]+s_[nt][1]; rs1+=s_[nt][2]+s_[nt][3];
        }
        rs0+=__shfl_xor_sync(0xffffffffu,rs0,1); rs0+=__shfl_xor_sync(0xffffffffu,rs0,2);
        rs1+=__shfl_xor_sync(0xffffffffu,rs1,1); rs1+=__shfl_xor_sync(0xffffffffu,rs1,2);
        l_run[0]=l_run[0]*al0+rs0; l_run[1]=l_run[1]*al1+rs1;
#pragma unroll
        for(int nt=0;nt<8;nt++){
            accR[nt][0]*=al0; accR[nt][1]*=al0; accR[nt][2]*=al1; accR[nt][3]*=al1;
            accI[nt][0]*=al0; accI[nt][1]*=al0; accI[nt][2]*=al1; accI[nt][3]*=al1;
        }
#pragma unroll
        for(int kc=0;kc<8;kc++){
            float x0=__shfl_sync(0xffffffffu,s_[kc][0],srcA);
            float x1=__shfl_sync(0xffffffffu,s_[kc][1],srcA);
            float z0=__shfl_sync(0xffffffffu,s_[kc][2],srcA);
            float z1=__shfl_sync(0xffffffffu,s_[kc][3],srcA);
            float y0=__shfl_sync(0xffffffffu,s_[kc][0],srcB);
            float y1=__shfl_sync(0xffffffffu,s_[kc][1],srcB);
            float w0=__shfl_sync(0xffffffffu,s_[kc][2],srcB);
            float w1=__shfl_sync(0xffffffffu,s_[kc][3],srcB);
            unsigned aP[4];
            aP[0]=__float_as_uint(odd?x1:x0);
            aP[1]=__float_as_uint(odd?z1:z0);
            aP[2]=__float_as_uint(odd?y1:y0);
            aP[3]=__float_as_uint(odd?w1:w0);
#pragma unroll
            for(int nt=0;nt<8;nt++){
                unsigned bR[2],bI[2];
                bR[0]=__float_as_uint(sVr[(8*kc+tg  )*WAP+8*nt+grp]);
                bR[1]=__float_as_uint(sVr[(8*kc+tg+4)*WAP+8*nt+grp]);
                bI[0]=__float_as_uint(sVi[(8*kc+tg  )*WAP+8*nt+grp]);
                bI[1]=__float_as_uint(sVi[(8*kc+tg+4)*WAP+8*nt+grp]);
                mma_tf32(accR[nt],aP,bR);
                mma_tf32(accI[nt],aP,bI);
            }
        }
        __syncthreads();
        if(jt+1<ntile){
            const int s0n=(jt+1)*64;
#pragma unroll
            for(int u=0;u<8;u++){
                int li=tid+u*128, r=li>>4, c4=(li&15)*4;
                size_t g=base+(size_t)(s0n+r)*Dsz+c4;
                CPA16(&sKr[r*WAP+c4], g_kr+g); CPA16(&sKi[r*WAP+c4], g_ki+g);
                CPA16(&sVr[r*WAP+c4], g_vr+g); CPA16(&sVi[r*WAP+c4], g_vi+g);
            }
            CPA_COMMIT();
        }
    }
    const float inv0=1.f/l_run[0], inv1=1.f/l_run[1];
#pragma unroll
    for(int nt=0;nt<8;nt++){
        const int d=nt*8+2*tg;
        size_t g0=base+(size_t)(i0+wrow+grp  )*Dsz+d;
        size_t g1=base+(size_t)(i0+wrow+grp+8)*Dsz+d;
        *(float2*)(g_ar+g0)=make_float2(accR[nt][0]*inv0,accR[nt][1]*inv0);
        *(float2*)(g_ar+g1)=make_float2(accR[nt][2]*inv1,accR[nt][3]*inv1);
        *(float2*)(g_ai+g0)=make_float2(accI[nt][0]*inv0,accI[nt][1]*inv0);
        *(float2*)(g_ai+g1)=make_float2(accI[nt][2]*inv1,accI[nt][3]*inv1);
    }
}

// ---------- tf32 VQ distance ----------
#define DAS_STRIDE (64*36)
#define DBS_STRIDE (128*36)
#define DBS_BASE   (2*DAS_STRIDE)
#define DIST_SMEM  ((2*DAS_STRIDE+2*DBS_STRIDE)*4)
__global__ __launch_bounds__(256) void dist_kernel(const float* __restrict__ cb) {
    extern __shared__ unsigned smd[];
    float2* sRed=(float2*)smd;
    const int m0=blockIdx.x*64;
    const int tid=threadIdx.x, warp=tid>>5, lane=tid&31;
    const int wm=warp>>2, wn=warp&3, grp=lane>>2, tg=lane&3;
    const int lrow=lane&15, lcol=(lane&16)?4:0;
    const int krow=((lane>>4)<<3)|(lane&7), kcol=((lane>>3)&1)*4;
    const int arow=tid>>3, ac4=(tid&7)*4;
    const int brow=tid>>3, bc4=(tid&7)*4;
    float acc[2][4][4];
#pragma unroll
    for(int i=0;i<2;i++)
#pragma unroll
        for(int j=0;j<4;j++)
#pragma unroll
            for(int k=0;k<4;k++) acc[i][j][k]=0.f;
#pragma unroll
    for(int u=0;u<2;u++)
        CPA16(&smd[(size_t)(arow+u*32)*36+ac4], g_pr+(size_t)(m0+arow+u*32)*Dsz+ac4);
#pragma unroll
    for(int u=0;u<4;u++)
        CPA16(&smd[DBS_BASE+(size_t)(brow+u*32)*36+bc4], cb+(size_t)(brow+u*32)*Dsz+bc4);
    CPA_COMMIT();
    const int NCHUNK=Dsz/32;
    for(int c=0;c<NCHUNK;c++){
        if(c+1<NCHUNK){
            const int st=(c+1)&1, kn=(c+1)*32;
            unsigned* dA=smd+(size_t)st*DAS_STRIDE;
            unsigned* dB=smd+DBS_BASE+(size_t)st*DBS_STRIDE;
#pragma unroll
            for(int u=0;u<2;u++)
                CPA16(&dA[(size_t)(arow+u*32)*36+ac4], g_pr+(size_t)(m0+arow+u*32)*Dsz+kn+ac4);
#pragma unroll
            for(int u=0;u<4;u++)
                CPA16(&dB[(size_t)(brow+u*32)*36+bc4], cb+(size_t)(brow+u*32)*Dsz+kn+bc4);
            CPA_COMMIT();
            CPA_WAIT1();
        } else CPA_WAIT0();
        __syncthreads();
        unsigned* As=smd+(size_t)(c&1)*DAS_STRIDE;
        unsigned* Bs=smd+DBS_BASE+(size_t)(c&1)*DBS_STRIDE;
#pragma unroll
        for(int k8=0;k8<4;k8++){
            const int kb8=k8*8;
            unsigned af[2][4];
#pragma unroll
            for(int mt=0;mt<2;mt++)
                LDSM4(af[mt], su32(&As[(size_t)(wm*32+mt*16+lrow)*36+kb8+lcol]));
#pragma unroll
            for(int ntp=0;ntp<2;ntp++){
                unsigned bf[4];
                LDSM4(bf, su32(&Bs[(size_t)(wn*32+16*ntp+krow)*36+kb8+kcol]));
#pragma unroll
                for(int mt=0;mt<2;mt++){
                    mma_tf32(acc[mt][2*ntp],  af[mt],&bf[0]);
                    mma_tf32(acc[mt][2*ntp+1],af[mt],&bf[2]);
                }
            }
        }
        __syncthreads();
    }
#pragma unroll
    for(int mt=0;mt<2;mt++){
        float bd0=1e30f,bd1=1e30f; int bi0=0,bi1=0;
#pragma unroll
        for(int nt=0;nt<4;nt++){
            int c0=wn*32+nt*8+2*tg, c1=c0+1;
            float d00=g_cn2[c0]-2.f*acc[mt][nt][0];
            float d01=g_cn2[c1]-2.f*acc[mt][nt][1];
            float d10=g_cn2[c0]-2.f*acc[mt][nt][2];
            float d11=g_cn2[c1]-2.f*acc[mt][nt][3];
            if(d00<bd0||(d00==bd0&&c0<bi0)){bd0=d00;bi0=c0;}
            if(d01<bd0||(d01==bd0&&c1<bi0)){bd0=d01;bi0=c1;}
            if(d10<bd1||(d10==bd1&&c0<bi1)){bd1=d10;bi1=c0;}
            if(d11<bd1||(d11==bd1&&c1<bi1)){bd1=d11;bi1=c1;}
        }
        int r0=wm*32+mt*16+grp, r1=r0+8;
        sRed[(size_t)r0*16+wn*4+tg]=make_float2(bd0,__int_as_float(bi0));
        sRed[(size_t)r1*16+wn*4+tg]=make_float2(bd1,__int_as_float(bi1));
    }
    __syncthreads();
    if(tid<64){
        float bd=1e30f; int bi=0;
#pragma unroll
        for(int t=0;t<16;t++){
            float2 e=sRed[(size_t)tid*16+t];
            int ix=__float_as_int(e.y);
            if(e.x<bd||(e.x==bd&&ix<bi)){bd=e.x;bi=ix;}
        }
        g_idx[m0+tid]=bi;
    }
}

// ---------- gated stack scan v2: 2 d-columns per warp ----------
__global__ __launch_bounds__(256) void scan_kernel(const float* __restrict__ cb) {
    __shared__ int sIdx[256]; __shared__ float sA[256],sB[256];
    __shared__ float sCB[NCsz][16];
    const int b=blockIdx.x>>5, dg=blockIdx.x&31;
    const int warp=threadIdx.x>>5, lane=threadIdx.x&31;
    const int d0=dg*16+warp*2, d1=d0+1;
#pragma unroll
    for(int u=0;u<8;u++){
        int li=threadIdx.x+u*256;
        int code=li>>4, w=li&15;
        sCB[code][w]=cb[(size_t)code*Dsz+dg*16+w];
    }
    float st0=0.f, st1=0.f;
    for(int t0=0;t0<Lsz;t0+=256){
        __syncthreads();
        int ix=g_idx[b*Lsz+t0+threadIdx.x];
        float p=g_gp[ix], o=g_go[ix];
        sIdx[threadIdx.x]=ix;
        sA[threadIdx.x]=(1.f-p)*(1.f-o);
        sB[threadIdx.x]=p*(1.f-o);
        __syncthreads();
        for(int tt=0;tt<256;tt++){
            int code=sIdx[tt];
            float a=sA[tt], bb=sB[tt];
            float v0=sCB[code][warp*2], v1=sCB[code][warp*2+1];
            float sh0=__shfl_down_sync(0xffffffffu,st0,1);
            float sh1=__shfl_down_sync(0xffffffffu,st1,1);
            if(lane==31){ sh0=v0; sh1=v1; }
            st0=fmaf(a,st0,bb*sh0);
            st1=fmaf(a,st1,bb*sh1);
            if(lane==31){
                size_t row=((size_t)b*Lsz+t0+tt)*Dsz;
                g_stk[row+d0]=st0; g_stk[row+d1]=st1;
            }
        }
    }
}

// ---------- final v2: 2 rows per 256-thread block ----------
__device__ __forceinline__ float halfRed(float v, float* s, int hwarp) {
#pragma unroll
    for(int o=16;o;o>>=1) v+=__shfl_xor_sync(0xffffffffu,v,o);
    if((threadIdx.x&31)==0) s[hwarp]=v;
    __syncthreads();
    v=s[0]+s[1]+s[2]+s[3];
    __syncthreads();
    return v;
}

__global__ __launch_bounds__(256) void final_kernel(const float* __restrict__ cb,
                             const float* __restrict__ lng,
                             const float* __restrict__ lnb,
                             const float* __restrict__ mb,
                             float* __restrict__ out) {
    __shared__ float swA[4], swB[4];
    const int half=threadIdx.x>>7, tid=threadIdx.x&127;
    const int hwarp=(threadIdx.x>>5)&3;
    const int m=blockIdx.x*2+half;
    float* sw = half? swB : swA;
    const float* pr=g_pr+(size_t)m*Dsz;
    const float4 c4=((const float4*)(cb+(size_t)g_idx[m]*Dsz))[tid];
    const float4 f4=((const float4*)pr)[tid];
    const float4 s4=((const float4*)(g_stk+(size_t)m*Dsz))[tid];
    const float4 i4=((const float4*)(g_pi+(size_t)m*Dsz))[tid];
    {
        float dx=c4.x-f4.x,dy=c4.y-f4.y,dz=c4.z-f4.z,dw=c4.w-f4.w;
        float lv=dx*dx+dy*dy+dz*dz+dw*dw;
        float lt=halfRed(lv,sw,hwarp);
        if(tid==0) atomicAdd(&g_loss,(double)lt);
    }
    float cr[4],ci[4];
    cr[0]=(f4.x+(c4.x-f4.x))+s4.x; cr[1]=(f4.y+(c4.y-f4.y))+s4.y;
    cr[2]=(f4.z+(c4.z-f4.z))+s4.z; cr[3]=(f4.w+(c4.w-f4.w))+s4.w;
    ci[0]=i4.x;ci[1]=i4.y;ci[2]=i4.z;ci[3]=i4.w;
    float sr=cr[0]+cr[1]+cr[2]+cr[3], si=ci[0]+ci[1]+ci[2]+ci[3];
    float mur=halfRed(sr,sw,hwarp)*(1.f/Dsz);
    float mui=halfRed(si,sw,hwarp)*(1.f/Dsz);
    float vr=0.f,vi=0.f;
#pragma unroll
    for(int k=0;k<4;k++){float a=cr[k]-mur,b=ci[k]-mui;vr+=a*a;vi+=b*b;}
    float varr=halfRed(vr,sw,hwarp)*(1.f/Dsz);
    float vari=halfRed(vi,sw,hwarp)*(1.f/Dsz);
    float rr=rsqrtf(varr+1e-5f), ri=rsqrtf(vari+1e-5f);
#pragma unroll
    for(int k=0;k<4;k++){
        int d=tid*4+k;
        float nr=(cr[k]-mur)*rr*lng[d]+lnb[d];
        float ni=(ci[k]-mui)*ri*lng[Dsz+d]+lnb[Dsz+d];
        float mag=sqrtf(nr*nr+ni*ni);
        float sc=fmaxf(mag+mb[d],0.f)/(mag+1e-6f);
        out[(size_t)m*Dsz+d]=nr*sc;
        out[OUTHALF+(size_t)m*Dsz+d]=ni*sc;
    }
}

__global__ void loss_write(float* __restrict__ out, long out_size){
    out[out_size-1]=(float)(1.25*g_loss/(double)((size_t)Msz*Dsz));
}

extern "C" void kernel_launch(void* const* d_in, const int* in_sizes, int n_in,
                              void* d_out, int out_size) {
    const int*   tokens=(const int*)  d_in[0];
    const float* embed =(const float*)d_in[2];
    const float* q_w=(const float*)d_in[3],  *q_b=(const float*)d_in[4];
    const float* k_w=(const float*)d_in[5],  *k_b=(const float*)d_in[6];
    const float* v_w=(const float*)d_in[7],  *v_b=(const float*)d_in[8];
    const float* o_w=(const float*)d_in[9],  *o_b=(const float*)d_in[10];
    const float* cb =(const float*)d_in[11];
    const float* gw =(const float*)d_in[12], *gb=(const float*)d_in[13];
    const float* lng=(const float*)d_in[14], *lnb=(const float*)d_in[15];
    const float* mb =(const float*)d_in[16];
    float* out=(float*)d_out;

    static bool attr_set=false;
    if(!attr_set){
        cudaFuncSetAttribute(attn_kernel,cudaFuncAttributeMaxDynamicSharedMemorySize,ATTN_SMEM);
        cudaFuncSetAttribute(proj_kernel,cudaFuncAttributeMaxDynamicSharedMemorySize,GEMM_SMEM);
        cudaFuncSetAttribute(oproj_kernel,cudaFuncAttributeMaxDynamicSharedMemorySize,GEMM_SMEM);
        cudaFuncSetAttribute(dist_kernel,cudaFuncAttributeMaxDynamicSharedMemorySize,DIST_SMEM);
        attr_set=true;
    }
    prep_kernel<<<NCsz,128>>>(cb,gw,gb);
    proj_kernel<<<dim3(4,64,6),256,GEMM_SMEM>>>(tokens,embed,q_w,q_b,k_w,k_b,v_w,v_b);
    attn_kernel<<<dim3(16,64),128,ATTN_SMEM>>>();
    oproj_kernel<<<dim3(8,64),256,GEMM_SMEM>>>(o_w,o_b);
    dist_kernel<<<128,256,DIST_SMEM>>>(cb);
    scan_kernel<<<256,256>>>(cb);
    final_kernel<<<Msz/2,256>>>(cb,lng,lnb,mb,out);
    loss_write<<<1,1>>>(out,(long)out_size);
}

// round 14
// speedup vs baseline: 1.1585x; 1.1585x over previous
#include <cuda_runtime.h>

#define Bsz 8
#define Lsz 1024
#define Dsz 512
#define HDsz 64
#define NCsz 128
#define Msz (Bsz*Lsz)
#define OUTHALF ((size_t)Msz*Dsz)
#define NEG_INF (-__int_as_float(0x7f800000))

__device__ float g_qr[Msz*Dsz], g_qi[Msz*Dsz];
__device__ float g_kr[Msz*Dsz], g_ki[Msz*Dsz];
__device__ float g_vr[Msz*Dsz], g_vi[Msz*Dsz];
__device__ float g_ar[Msz*Dsz], g_ai[Msz*Dsz];
__device__ float g_pr[Msz*Dsz], g_pi[Msz*Dsz];
__device__ int   g_idx[Msz];
__device__ float g_stk[Msz*Dsz];
__device__ float g_cn2[NCsz], g_gp[NCsz], g_go[NCsz];
__device__ double g_loss;

__device__ __forceinline__ void mma_tf32(float* c, const unsigned* a, const unsigned* b){
    asm volatile("mma.sync.aligned.m16n8k8.row.col.f32.tf32.tf32.f32 "
        "{%0,%1,%2,%3}, {%4,%5,%6,%7}, {%8,%9}, {%0,%1,%2,%3};"
        : "+f"(c[0]),"+f"(c[1]),"+f"(c[2]),"+f"(c[3])
        : "r"(a[0]),"r"(a[1]),"r"(a[2]),"r"(a[3]),"r"(b[0]),"r"(b[1]));
}
__device__ __forceinline__ unsigned su32(const void* p){
    return (unsigned)__cvta_generic_to_shared(p);
}
#define LDSM4(r,a) asm volatile("ldmatrix.sync.aligned.m8n8.x4.shared.b16 {%0,%1,%2,%3}, [%4];" \
    : "=r"((r)[0]),"=r"((r)[1]),"=r"((r)[2]),"=r"((r)[3]) : "r"(a))
#define CPA16(dst,src) asm volatile("cp.async.cg.shared.global [%0], [%1], 16;" :: "r"(su32(dst)), "l"(src))
#define CPA_COMMIT()   asm volatile("cp.async.commit_group;" ::: "memory")
#define CPA_WAIT0()    asm volatile("cp.async.wait_group 0;" ::: "memory")
#define CPA_WAIT1()    asm volatile("cp.async.wait_group 1;" ::: "memory")

#define AS_STRIDE (128*36)
#define BS_STRIDE (32*132)
#define BS_BASE   (2*AS_STRIDE)
#define GEMM_SMEM ((2*AS_STRIDE+2*BS_STRIDE)*4)

// ---------- prep ----------
__global__ void prep_kernel(const float* __restrict__ cb,
                            const float* __restrict__ gw,
                            const float* __restrict__ gb) {
    __shared__ float sh[3][4];
    const int j=blockIdx.x, t=threadIdx.x;
    if(j==0&&t==0) g_loss=0.0;
    float s2=0.f,d0=0.f,d1=0.f;
    for(int d=t; d<Dsz; d+=128){
        float c=cb[j*Dsz+d];
        s2+=c*c; d0+=c*gw[2*d]; d1+=c*gw[2*d+1];
    }
#pragma unroll
    for(int o=16;o;o>>=1){
        s2+=__shfl_xor_sync(0xffffffffu,s2,o);
        d0+=__shfl_xor_sync(0xffffffffu,d0,o);
        d1+=__shfl_xor_sync(0xffffffffu,d1,o);
    }
    if((t&31)==0){ sh[0][t>>5]=s2; sh[1][t>>5]=d0; sh[2][t>>5]=d1; }
    __syncthreads();
    if(t==0){
        float a=sh[0][0]+sh[0][1]+sh[0][2]+sh[0][3];
        float b=sh[1][0]+sh[1][1]+sh[1][2]+sh[1][3];
        float c=sh[2][0]+sh[2][1]+sh[2][2]+sh[2][3];
        g_cn2[j]=a;
        g_gp[j]=1.f/(1.f+expf(-(b+gb[0])));
        g_go[j]=1.f/(1.f+expf(-(c+gb[1])));
    }
}

// ---------- tf32 projection GEMM: cp.async 2-stage, fused gather ----------
__global__ __launch_bounds__(256) void proj_kernel(
        const int* __restrict__ tokens, const float* __restrict__ embed,
        const float* __restrict__ qw, const float* __restrict__ qb,
        const float* __restrict__ kw, const float* __restrict__ kb,
        const float* __restrict__ vw, const float* __restrict__ vb) {
    extern __shared__ unsigned smg[];
    const int z = blockIdx.z, pair = z>>1, im = z&1;
    const float* W; const float* bias; float* C;
    if (pair==0){W=qw;bias=qb;C=im?g_qi:g_qr;}
    else if (pair==1){W=kw;bias=kb;C=im?g_ki:g_kr;}
    else {W=vw;bias=vb;C=im?g_vi:g_vr;}
    W += (size_t)im*Dsz*Dsz;
    const float sgn = im?1.f:-1.f;
    const int m0=blockIdx.y*128, n0=blockIdx.x*128;
    const int tid=threadIdx.x, warp=tid>>5, lane=tid&31;
    const int wm=warp>>2, wn=warp&3, grp=lane>>2, tg=lane&3;
    const int lrow=lane&15, lcol=(lane&16)?4:0;
    const int arow=tid>>3, ac4=(tid&7)*4;
    const int brow=tid>>5, bc4=(tid&31)*4;
    size_t aoff[4];
#pragma unroll
    for(int u=0;u<4;u++)
        aoff[u]=(size_t)tokens[m0+arow+u*32]*Dsz;
    float acc[4][4][4];
#pragma unroll
    for(int i=0;i<4;i++)
#pragma unroll
        for(int j=0;j<4;j++)
#pragma unroll
            for(int k=0;k<4;k++) acc[i][j][k]=0.f;
#pragma unroll
    for(int u=0;u<4;u++){
        CPA16(&smg[(size_t)(arow+u*32)*36+ac4], embed+aoff[u]+ac4);
        CPA16(&smg[BS_BASE+(size_t)(brow+u*8)*132+bc4], W+(size_t)(brow+u*8)*Dsz+n0+bc4);
    }
    CPA_COMMIT();
    const int NCHUNK=Dsz/32;
    for(int c=0;c<NCHUNK;c++){
        if(c+1<NCHUNK){
            const int st=(c+1)&1, kn=(c+1)*32;
            unsigned* dA=smg+(size_t)st*AS_STRIDE;
            unsigned* dB=smg+BS_BASE+(size_t)st*BS_STRIDE;
#pragma unroll
            for(int u=0;u<4;u++){
                CPA16(&dA[(size_t)(arow+u*32)*36+ac4], embed+aoff[u]+kn+ac4);
                CPA16(&dB[(size_t)(brow+u*8)*132+bc4], W+(size_t)(kn+brow+u*8)*Dsz+n0+bc4);
            }
            CPA_COMMIT();
            CPA_WAIT1();
        } else CPA_WAIT0();
        __syncthreads();
        unsigned* As=smg+(size_t)(c&1)*AS_STRIDE;
        unsigned* Bs=smg+BS_BASE+(size_t)(c&1)*BS_STRIDE;
#pragma unroll
        for(int k8=0;k8<4;k8++){
            const int kb8=k8*8;
            unsigned af[4][4], bf[4][2];
#pragma unroll
            for(int mt=0;mt<4;mt++)
                LDSM4(af[mt], su32(&As[(size_t)(wm*64+mt*16+lrow)*36+kb8+lcol]));
#pragma unroll
            for(int nt=0;nt<4;nt++){
                int cix=wn*32+nt*8+grp;
                bf[nt][0]=Bs[(size_t)(kb8+tg)*132+cix]; bf[nt][1]=Bs[(size_t)(kb8+tg+4)*132+cix];
            }
#pragma unroll
            for(int mt=0;mt<4;mt++)
#pragma unroll
                for(int nt=0;nt<4;nt++) mma_tf32(acc[mt][nt],af[mt],bf[nt]);
        }
        __syncthreads();
    }
#pragma unroll
    for(int mt=0;mt<4;mt++){
#pragma unroll
        for(int nt=0;nt<4;nt++){
            int r=m0+wm*64+mt*16+grp;
            int cix=n0+wn*32+nt*8+2*tg;
            float b0=bias[cix]+sgn*bias[Dsz+cix];
            float b1=bias[cix+1]+sgn*bias[Dsz+cix+1];
            *(float2*)(C+(size_t)r*Dsz+cix)    =make_float2(acc[mt][nt][0]+b0,acc[mt][nt][1]+b1);
            *(float2*)(C+(size_t)(r+8)*Dsz+cix)=make_float2(acc[mt][nt][2]+b0,acc[mt][nt][3]+b1);
        }
    }
}

// ---------- tf32 fused complex O-projection: cp.async 2-stage, sign on A ----------
__global__ __launch_bounds__(256) void oproj_kernel(const float* __restrict__ ow,
                                                    const float* __restrict__ ob) {
    extern __shared__ unsigned smg[];
    const float* w0=ow; const float* w1=ow+(size_t)Dsz*Dsz;
    const int m0=blockIdx.y*128, n0=blockIdx.x*128;
    const bool isI = (n0>=Dsz);
    const int nloc = isI ? n0-Dsz : n0;
    const int tid=threadIdx.x, warp=tid>>5, lane=tid&31;
    const int wm=warp>>2, wn=warp&3, grp=lane>>2, tg=lane&3;
    const int lrow=lane&15, lcol=(lane&16)?4:0;
    const int arow=tid>>3, ac4=(tid&7)*4;
    const int brow=tid>>5, bc4=(tid&31)*4;
    float acc[4][4][4];
#pragma unroll
    for(int i=0;i<4;i++)
#pragma unroll
        for(int j=0;j<4;j++)
#pragma unroll
            for(int k=0;k<4;k++) acc[i][j][k]=0.f;
    const int NCHUNK=2*Dsz/32;
#pragma unroll
    for(int u=0;u<4;u++){
        const float* wsrc = isI ? w1 : w0;
        CPA16(&smg[(size_t)(arow+u*32)*36+ac4], g_ar+(size_t)(m0+arow+u*32)*Dsz+ac4);
        CPA16(&smg[BS_BASE+(size_t)(brow+u*8)*132+bc4], wsrc+(size_t)(brow+u*8)*Dsz+nloc+bc4);
    }
    CPA_COMMIT();
    for(int c=0;c<NCHUNK;c++){
        if(c+1<NCHUNK){
            const int st=(c+1)&1, kn=(c+1)*32;
            const bool khi=(kn>=Dsz);
            const float* asrc = khi ? g_ai : g_ar;
            const int akk = khi ? kn-Dsz : kn;
            const float* wsrc = isI ? (khi ? w0 : w1) : (khi ? w1 : w0);
            const int bkk = khi ? kn-Dsz : kn;
            unsigned* dA=smg+(size_t)st*AS_STRIDE;
            unsigned* dB=smg+BS_BASE+(size_t)st*BS_STRIDE;
#pragma unroll
            for(int u=0;u<4;u++){
                CPA16(&dA[(size_t)(arow+u*32)*36+ac4], asrc+(size_t)(m0+arow+u*32)*Dsz+akk+ac4);
                CPA16(&dB[(size_t)(brow+u*8)*132+bc4], wsrc+(size_t)(bkk+brow+u*8)*Dsz+nloc+bc4);
            }
            CPA_COMMIT();
            CPA_WAIT1();
        } else CPA_WAIT0();
        __syncthreads();
        const bool negA = (!isI) && (c>=NCHUNK/2);
        unsigned* As=smg+(size_t)(c&1)*AS_STRIDE;
        unsigned* Bs=smg+BS_BASE+(size_t)(c&1)*BS_STRIDE;
#pragma unroll
        for(int k8=0;k8<4;k8++){
            const int kb8=k8*8;
            unsigned af[4][4], bf[4][2];
#pragma unroll
            for(int mt=0;mt<4;mt++){
                LDSM4(af[mt], su32(&As[(size_t)(wm*64+mt*16+lrow)*36+kb8+lcol]));
                if(negA){
                    af[mt][0]^=0x80000000u; af[mt][1]^=0x80000000u;
                    af[mt][2]^=0x80000000u; af[mt][3]^=0x80000000u;
                }
            }
#pragma unroll
            for(int nt=0;nt<4;nt++){
                int cix=wn*32+nt*8+grp;
                bf[nt][0]=Bs[(size_t)(kb8+tg)*132+cix]; bf[nt][1]=Bs[(size_t)(kb8+tg+4)*132+cix];
            }
#pragma unroll
            for(int mt=0;mt<4;mt++)
#pragma unroll
                for(int nt=0;nt<4;nt++) mma_tf32(acc[mt][nt],af[mt],bf[nt]);
        }
        __syncthreads();
    }
    float* Cdst = isI ? g_pi : g_pr;
    const float s2 = isI ? 1.f : -1.f;
#pragma unroll
    for(int mt=0;mt<4;mt++){
#pragma unroll
        for(int nt=0;nt<4;nt++){
            int r=m0+wm*64+mt*16+grp;
            int cl=wn*32+nt*8+2*tg;
            int cg=nloc+cl;
            float b0=ob[cg]+s2*ob[Dsz+cg];
            float b1=ob[cg+1]+s2*ob[Dsz+cg+1];
            *(float2*)(Cdst+(size_t)r*Dsz+cg)    =make_float2(acc[mt][nt][0]+b0,acc[mt][nt][1]+b1);
            *(float2*)(Cdst+(size_t)(r+8)*Dsz+cg)=make_float2(acc[mt][nt][2]+b0,acc[mt][nt][3]+b1);
        }
    }
}

// ---------- tf32 flash attention v4 ----------
#define WAP 68
#define ATTN_SMEM (6*64*WAP*4)
__global__ __launch_bounds__(128) void attn_kernel() {
    extern __shared__ float smf[];
    float* sQr=smf;             float* sQi=sQr+64*WAP;
    float* sKr=sQi+64*WAP;      float* sKi=sKr+64*WAP;
    float* sVr=sKi+64*WAP;      float* sVi=sVr+64*WAP;
    const int bh=blockIdx.y, b=bh>>3, h=bh&7;
    const int bx=blockIdx.x, i0=bx*64;
    const int tid=threadIdx.x, warp=tid>>5, lane=tid&31;
    const int grp=lane>>2, tg=lane&3;
    const int lrow=lane&15, lcol=(lane&16)?4:0;
    const int krow=((lane>>4)<<3)|(lane&7), kcol=((lane>>3)&1)*4;
    const int wrow=warp*16;
    const size_t base=(size_t)b*Lsz*Dsz + h*HDsz;
#pragma unroll
    for(int u=0;u<8;u++){
        int li=tid+u*128, r=li>>4, c4=(li&15)*4;
        size_t g=base+(size_t)(i0+r)*Dsz+c4;
        CPA16(&sQr[r*WAP+c4], g_qr+g);
        CPA16(&sQi[r*WAP+c4], g_qi+g);
    }
    CPA_COMMIT();
    const int ntile=bx+1;
#pragma unroll
    for(int u=0;u<8;u++){
        int li=tid+u*128, r=li>>4, c4=(li&15)*4;
        size_t g=base+(size_t)r*Dsz+c4;
        CPA16(&sKr[r*WAP+c4], g_kr+g); CPA16(&sKi[r*WAP+c4], g_ki+g);
        CPA16(&sVr[r*WAP+c4], g_vr+g); CPA16(&sVi[r*WAP+c4], g_vi+g);
    }
    CPA_COMMIT();
    float m_run[2]={NEG_INF,NEG_INF}, l_run[2]={0.f,0.f};
    float accR[8][4], accI[8][4];
#pragma unroll
    for(int nt=0;nt<8;nt++)
#pragma unroll
        for(int k=0;k<4;k++){accR[nt][k]=0.f;accI[nt][k]=0.f;}
    const int srcA=(lane&~3)|(tg>>1), srcB=srcA|2;
    const bool odd=tg&1;
    for(int jt=0;jt<ntile;jt++){
        CPA_WAIT0();
        __syncthreads();
        const int s0=jt*64;
        float s_[8][4];
#pragma unroll
        for(int nt=0;nt<8;nt++)
#pragma unroll
            for(int k=0;k<4;k++) s_[nt][k]=0.f;
#pragma unroll
        for(int kc=0;kc<8;kc++){
            const int kb=kc*8;
            unsigned aR[4],aI[4];
            LDSM4(aR, su32(&sQr[(wrow+lrow)*WAP+kb+lcol]));
            LDSM4(aI, su32(&sQi[(wrow+lrow)*WAP+kb+lcol]));
#pragma unroll
            for(int ntp=0;ntp<4;ntp++){
                unsigned kR[4],kI[4];
                LDSM4(kR, su32(&sKr[(16*ntp+krow)*WAP+kb+kcol]));
                LDSM4(kI, su32(&sKi[(16*ntp+krow)*WAP+kb+kcol]));
                mma_tf32(s_[2*ntp],  aR,&kR[0]); mma_tf32(s_[2*ntp],  aI,&kI[0]);
                mma_tf32(s_[2*ntp+1],aR,&kR[2]); mma_tf32(s_[2*ntp+1],aI,&kI[2]);
            }
        }
        const bool diag=(jt==bx);
        const int r0=i0+wrow+grp, r1=r0+8;
#pragma unroll
        for(int nt=0;nt<8;nt++){
            const int c0=s0+nt*8+2*tg, c1=c0+1;
            s_[nt][0]*=0.125f; s_[nt][1]*=0.125f; s_[nt][2]*=0.125f; s_[nt][3]*=0.125f;
            if(diag){
                if(c0>r0)s_[nt][0]=NEG_INF; if(c1>r0)s_[nt][1]=NEG_INF;
                if(c0>r1)s_[nt][2]=NEG_INF; if(c1>r1)s_[nt][3]=NEG_INF;
            }
        }
        float mx0=NEG_INF, mx1=NEG_INF;
#pragma unroll
        for(int nt=0;nt<8;nt++){
            mx0=fmaxf(mx0,fmaxf(s_[nt][0],s_[nt][1]));
            mx1=fmaxf(mx1,fmaxf(s_[nt][2],s_[nt][3]));
        }
        mx0=fmaxf(mx0,__shfl_xor_sync(0xffffffffu,mx0,1));
        mx0=fmaxf(mx0,__shfl_xor_sync(0xffffffffu,mx0,2));
        mx1=fmaxf(mx1,__shfl_xor_sync(0xffffffffu,mx1,1));
        mx1=fmaxf(mx1,__shfl_xor_sync(0xffffffffu,mx1,2));
        const float mn0=fmaxf(m_run[0],mx0), mn1=fmaxf(m_run[1],mx1);
        const float al0=__expf(m_run[0]-mn0), al1=__expf(m_run[1]-mn1);
        m_run[0]=mn0; m_run[1]=mn1;
        float rs0=0.f, rs1=0.f;
#pragma unroll
        for(int nt=0;nt<8;nt++){
            s_[nt][0]=__expf(s_[nt][0]-mn0); s_[nt][1]=__expf(s_[nt][1]-mn0);
            s_[nt][2]=__expf(s_[nt][2]-mn1); s_[nt][3]=__expf(s_[nt][3]-mn1);
            rs0+=s_[nt][0]+s_[nt][1]; rs1+=s_[nt][2]+s_[nt][3];
        }
        rs0+=__shfl_xor_sync(0xffffffffu,rs0,1); rs0+=__shfl_xor_sync(0xffffffffu,rs0,2);
        rs1+=__shfl_xor_sync(0xffffffffu,rs1,1); rs1+=__shfl_xor_sync(0xffffffffu,rs1,2);
        l_run[0]=l_run[0]*al0+rs0; l_run[1]=l_run[1]*al1+rs1;
#pragma unroll
        for(int nt=0;nt<8;nt++){
            accR[nt][0]*=al0; accR[nt][1]*=al0; accR[nt][2]*=al1; accR[nt][3]*=al1;
            accI[nt][0]*=al0; accI[nt][1]*=al0; accI[nt][2]*=al1; accI[nt][3]*=al1;
        }
#pragma unroll
        for(int kc=0;kc<8;kc++){
            float x0=__shfl_sync(0xffffffffu,s_[kc][0],srcA);
            float x1=__shfl_sync(0xffffffffu,s_[kc][1],srcA);
            float z0=__shfl_sync(0xffffffffu,s_[kc][2],srcA);
            float z1=__shfl_sync(0xffffffffu,s_[kc][3],srcA);
            float y0=__shfl_sync(0xffffffffu,s_[kc][0],srcB);
            float y1=__shfl_sync(0xffffffffu,s_[kc][1],srcB);
            float w0=__shfl_sync(0xffffffffu,s_[kc][2],srcB);
            float w1=__shfl_sync(0xffffffffu,s_[kc][3],srcB);
            unsigned aP[4];
            aP[0]=__float_as_uint(odd?x1:x0);
            aP[1]=__float_as_uint(odd?z1:z0);
            aP[2]=__float_as_uint(odd?y1:y0);
            aP[3]=__float_as_uint(odd?w1:w0);
#pragma unroll
            for(int nt=0;nt<8;nt++){
                unsigned bR[2],bI[2];
                bR[0]=__float_as_uint(sVr[(8*kc+tg  )*WAP+8*nt+grp]);
                bR[1]=__float_as_uint(sVr[(8*kc+tg+4)*WAP+8*nt+grp]);
                bI[0]=__float_as_uint(sVi[(8*kc+tg  )*WAP+8*nt+grp]);
                bI[1]=__float_as_uint(sVi[(8*kc+tg+4)*WAP+8*nt+grp]);
                mma_tf32(accR[nt],aP,bR);
                mma_tf32(accI[nt],aP,bI);
            }
        }
        __syncthreads();
        if(jt+1<ntile){
            const int s0n=(jt+1)*64;
#pragma unroll
            for(int u=0;u<8;u++){
                int li=tid+u*128, r=li>>4, c4=(li&15)*4;
                size_t g=base+(size_t)(s0n+r)*Dsz+c4;
                CPA16(&sKr[r*WAP+c4], g_kr+g); CPA16(&sKi[r*WAP+c4], g_ki+g);
                CPA16(&sVr[r*WAP+c4], g_vr+g); CPA16(&sVi[r*WAP+c4], g_vi+g);
            }
            CPA_COMMIT();
        }
    }
    const float inv0=1.f/l_run[0], inv1=1.f/l_run[1];
#pragma unroll
    for(int nt=0;nt<8;nt++){
        const int d=nt*8+2*tg;
        size_t g0=base+(size_t)(i0+wrow+grp  )*Dsz+d;
        size_t g1=base+(size_t)(i0+wrow+grp+8)*Dsz+d;
        *(float2*)(g_ar+g0)=make_float2(accR[nt][0]*inv0,accR[nt][1]*inv0);
        *(float2*)(g_ar+g1)=make_float2(accR[nt][2]*inv1,accR[nt][3]*inv1);
        *(float2*)(g_ai+g0)=make_float2(accI[nt][0]*inv0,accI[nt][1]*inv0);
        *(float2*)(g_ai+g1)=make_float2(accI[nt][2]*inv1,accI[nt][3]*inv1);
    }
}

// ---------- tf32 VQ distance ----------
#define DAS_STRIDE (64*36)
#define DBS_STRIDE (128*36)
#define DBS_BASE   (2*DAS_STRIDE)
#define DIST_SMEM  ((2*DAS_STRIDE+2*DBS_STRIDE)*4)
__global__ __launch_bounds__(256) void dist_kernel(const float* __restrict__ cb) {
    extern __shared__ unsigned smd[];
    float2* sRed=(float2*)smd;
    const int m0=blockIdx.x*64;
    const int tid=threadIdx.x, warp=tid>>5, lane=tid&31;
    const int wm=warp>>2, wn=warp&3, grp=lane>>2, tg=lane&3;
    const int lrow=lane&15, lcol=(lane&16)?4:0;
    const int krow=((lane>>4)<<3)|(lane&7), kcol=((lane>>3)&1)*4;
    const int arow=tid>>3, ac4=(tid&7)*4;
    const int brow=tid>>3, bc4=(tid&7)*4;
    float acc[2][4][4];
#pragma unroll
    for(int i=0;i<2;i++)
#pragma unroll
        for(int j=0;j<4;j++)
#pragma unroll
            for(int k=0;k<4;k++) acc[i][j][k]=0.f;
#pragma unroll
    for(int u=0;u<2;u++)
        CPA16(&smd[(size_t)(arow+u*32)*36+ac4], g_pr+(size_t)(m0+arow+u*32)*Dsz+ac4);
#pragma unroll
    for(int u=0;u<4;u++)
        CPA16(&smd[DBS_BASE+(size_t)(brow+u*32)*36+bc4], cb+(size_t)(brow+u*32)*Dsz+bc4);
    CPA_COMMIT();
    const int NCHUNK=Dsz/32;
    for(int c=0;c<NCHUNK;c++){
        if(c+1<NCHUNK){
            const int st=(c+1)&1, kn=(c+1)*32;
            unsigned* dA=smd+(size_t)st*DAS_STRIDE;
            unsigned* dB=smd+DBS_BASE+(size_t)st*DBS_STRIDE;
#pragma unroll
            for(int u=0;u<2;u++)
                CPA16(&dA[(size_t)(arow+u*32)*36+ac4], g_pr+(size_t)(m0+arow+u*32)*Dsz+kn+ac4);
#pragma unroll
            for(int u=0;u<4;u++)
                CPA16(&dB[(size_t)(brow+u*32)*36+bc4], cb+(size_t)(brow+u*32)*Dsz+kn+bc4);
            CPA_COMMIT();
            CPA_WAIT1();
        } else CPA_WAIT0();
        __syncthreads();
        unsigned* As=smd+(size_t)(c&1)*DAS_STRIDE;
        unsigned* Bs=smd+DBS_BASE+(size_t)(c&1)*DBS_STRIDE;
#pragma unroll
        for(int k8=0;k8<4;k8++){
            const int kb8=k8*8;
            unsigned af[2][4];
#pragma unroll
            for(int mt=0;mt<2;mt++)
                LDSM4(af[mt], su32(&As[(size_t)(wm*32+mt*16+lrow)*36+kb8+lcol]));
#pragma unroll
            for(int ntp=0;ntp<2;ntp++){
                unsigned bf[4];
                LDSM4(bf, su32(&Bs[(size_t)(wn*32+16*ntp+krow)*36+kb8+kcol]));
#pragma unroll
                for(int mt=0;mt<2;mt++){
                    mma_tf32(acc[mt][2*ntp],  af[mt],&bf[0]);
                    mma_tf32(acc[mt][2*ntp+1],af[mt],&bf[2]);
                }
            }
        }
        __syncthreads();
    }
#pragma unroll
    for(int mt=0;mt<2;mt++){
        float bd0=1e30f,bd1=1e30f; int bi0=0,bi1=0;
#pragma unroll
        for(int nt=0;nt<4;nt++){
            int c0=wn*32+nt*8+2*tg, c1=c0+1;
            float d00=g_cn2[c0]-2.f*acc[mt][nt][0];
            float d01=g_cn2[c1]-2.f*acc[mt][nt][1];
            float d10=g_cn2[c0]-2.f*acc[mt][nt][2];
            float d11=g_cn2[c1]-2.f*acc[mt][nt][3];
            if(d00<bd0||(d00==bd0&&c0<bi0)){bd0=d00;bi0=c0;}
            if(d01<bd0||(d01==bd0&&c1<bi0)){bd0=d01;bi0=c1;}
            if(d10<bd1||(d10==bd1&&c0<bi1)){bd1=d10;bi1=c0;}
            if(d11<bd1||(d11==bd1&&c1<bi1)){bd1=d11;bi1=c1;}
        }
        int r0=wm*32+mt*16+grp, r1=r0+8;
        sRed[(size_t)r0*16+wn*4+tg]=make_float2(bd0,__int_as_float(bi0));
        sRed[(size_t)r1*16+wn*4+tg]=make_float2(bd1,__int_as_float(bi1));
    }
    __syncthreads();
    if(tid<64){
        float bd=1e30f; int bi=0;
#pragma unroll
        for(int t=0;t<16;t++){
            float2 e=sRed[(size_t)tid*16+t];
            int ix=__float_as_int(e.y);
            if(e.x<bd||(e.x==bd&&ix<bi)){bd=e.x;bi=ix;}
        }
        g_idx[m0+tid]=bi;
    }
}

// ---------- gated stack scan v2: 2 d-columns per warp ----------
__global__ __launch_bounds__(256) void scan_kernel(const float* __restrict__ cb) {
    __shared__ int sIdx[256]; __shared__ float sA[256],sB[256];
    __shared__ float sCB[NCsz][16];
    const int b=blockIdx.x>>5, dg=blockIdx.x&31;
    const int warp=threadIdx.x>>5, lane=threadIdx.x&31;
    const int d0=dg*16+warp*2, d1=d0+1;
#pragma unroll
    for(int u=0;u<8;u++){
        int li=threadIdx.x+u*256;
        int code=li>>4, w=li&15;
        sCB[code][w]=cb[(size_t)code*Dsz+dg*16+w];
    }
    float st0=0.f, st1=0.f;
    for(int t0=0;t0<Lsz;t0+=256){
        __syncthreads();
        int ix=g_idx[b*Lsz+t0+threadIdx.x];
        float p=g_gp[ix], o=g_go[ix];
        sIdx[threadIdx.x]=ix;
        sA[threadIdx.x]=(1.f-p)*(1.f-o);
        sB[threadIdx.x]=p*(1.f-o);
        __syncthreads();
        for(int tt=0;tt<256;tt++){
            int code=sIdx[tt];
            float a=sA[tt], bb=sB[tt];
            float v0=sCB[code][warp*2], v1=sCB[code][warp*2+1];
            float sh0=__shfl_down_sync(0xffffffffu,st0,1);
            float sh1=__shfl_down_sync(0xffffffffu,st1,1);
            if(lane==31){ sh0=v0; sh1=v1; }
            st0=fmaf(a,st0,bb*sh0);
            st1=fmaf(a,st1,bb*sh1);
            if(lane==31){
                size_t row=((size_t)b*Lsz+t0+tt)*Dsz;
                g_stk[row+d0]=st0; g_stk[row+d1]=st1;
            }
        }
    }
}

// ---------- final v2: 2 rows per 256-thread block ----------
__device__ __forceinline__ float halfRed(float v, float* s, int hwarp) {
#pragma unroll
    for(int o=16;o;o>>=1) v+=__shfl_xor_sync(0xffffffffu,v,o);
    if((threadIdx.x&31)==0) s[hwarp]=v;
    __syncthreads();
    v=s[0]+s[1]+s[2]+s[3];
    __syncthreads();
    return v;
}

__global__ __launch_bounds__(256) void final_kernel(const float* __restrict__ cb,
                             const float* __restrict__ lng,
                             const float* __restrict__ lnb,
                             const float* __restrict__ mb,
                             float* __restrict__ out) {
    __shared__ float swA[4], swB[4];
    const int half=threadIdx.x>>7, tid=threadIdx.x&127;
    const int hwarp=(threadIdx.x>>5)&3;
    const int m=blockIdx.x*2+half;
    float* sw = half? swB : swA;
    const float* pr=g_pr+(size_t)m*Dsz;
    const float4 c4=((const float4*)(cb+(size_t)g_idx[m]*Dsz))[tid];
    const float4 f4=((const float4*)pr)[tid];
    const float4 s4=((const float4*)(g_stk+(size_t)m*Dsz))[tid];
    const float4 i4=((const float4*)(g_pi+(size_t)m*Dsz))[tid];
    {
        float dx=c4.x-f4.x,dy=c4.y-f4.y,dz=c4.z-f4.z,dw=c4.w-f4.w;
        float lv=dx*dx+dy*dy+dz*dz+dw*dw;
        float lt=halfRed(lv,sw,hwarp);
        if(tid==0) atomicAdd(&g_loss,(double)lt);
    }
    float cr[4],ci[4];
    cr[0]=(f4.x+(c4.x-f4.x))+s4.x; cr[1]=(f4.y+(c4.y-f4.y))+s4.y;
    cr[2]=(f4.z+(c4.z-f4.z))+s4.z; cr[3]=(f4.w+(c4.w-f4.w))+s4.w;
    ci[0]=i4.x;ci[1]=i4.y;ci[2]=i4.z;ci[3]=i4.w;
    float sr=cr[0]+cr[1]+cr[2]+cr[3], si=ci[0]+ci[1]+ci[2]+ci[3];
    float mur=halfRed(sr,sw,hwarp)*(1.f/Dsz);
    float mui=halfRed(si,sw,hwarp)*(1.f/Dsz);
    float vr=0.f,vi=0.f;
#pragma unroll
    for(int k=0;k<4;k++){float a=cr[k]-mur,b=ci[k]-mui;vr+=a*a;vi+=b*b;}
    float varr=halfRed(vr,sw,hwarp)*(1.f/Dsz);
    float vari=halfRed(vi,sw,hwarp)*(1.f/Dsz);
    float rr=rsqrtf(varr+1e-5f), ri=rsqrtf(vari+1e-5f);
#pragma unroll
    for(int k=0;k<4;k++){
        int d=tid*4+k;
        float nr=(cr[k]-mur)*rr*lng[d]+lnb[d];
        float ni=(ci[k]-mui)*ri*lng[Dsz+d]+lnb[Dsz+d];
        float mag=sqrtf(nr*nr+ni*ni);
        float sc=fmaxf(mag+mb[d],0.f)/(mag+1e-6f);
        out[(size_t)m*Dsz+d]=nr*sc;
        out[OUTHALF+(size_t)m*Dsz+d]=ni*sc;
    }
}

__global__ void loss_write(float* __restrict__ out, long out_size){
    out[out_size-1]=(float)(1.25*g_loss/(double)((size_t)Msz*Dsz));
}

extern "C" void kernel_launch(void* const* d_in, const int* in_sizes, int n_in,
                              void* d_out, int out_size) {
    const int*   tokens=(const int*)  d_in[0];
    const float* embed =(const float*)d_in[2];
    const float* q_w=(const float*)d_in[3],  *q_b=(const float*)d_in[4];
    const float* k_w=(const float*)d_in[5],  *k_b=(const float*)d_in[6];
    const float* v_w=(const float*)d_in[7],  *v_b=(const float*)d_in[8];
    const float* o_w=(const float*)d_in[9],  *o_b=(const float*)d_in[10];
    const float* cb =(const float*)d_in[11];
    const float* gw =(const float*)d_in[12], *gb=(const float*)d_in[13];
    const float* lng=(const float*)d_in[14], *lnb=(const float*)d_in[15];
    const float* mb =(const float*)d_in[16];
    float* out=(float*)d_out;

    static bool attr_set=false;
    if(!attr_set){
        cudaFuncSetAttribute(attn_kernel,cudaFuncAttributeMaxDynamicSharedMemorySize,ATTN_SMEM);
        cudaFuncSetAttribute(proj_kernel,cudaFuncAttributeMaxDynamicSharedMemorySize,GEMM_SMEM);
        cudaFuncSetAttribute(oproj_kernel,cudaFuncAttributeMaxDynamicSharedMemorySize,GEMM_SMEM);
        cudaFuncSetAttribute(dist_kernel,cudaFuncAttributeMaxDynamicSharedMemorySize,DIST_SMEM);
        attr_set=true;
    }
    prep_kernel<<<NCsz,128>>>(cb,gw,gb);
    proj_kernel<<<dim3(4,64,6),256,GEMM_SMEM>>>(tokens,embed,q_w,q_b,k_w,k_b,v_w,v_b);
    attn_kernel<<<dim3(16,64),128,ATTN_SMEM>>>();
    oproj_kernel<<<dim3(8,64),256,GEMM_SMEM>>>(o_w,o_b);
    dist_kernel<<<128,256,DIST_SMEM>>>(cb);
    scan_kernel<<<256,256>>>(cb);
    final_kernel<<<Msz/2,256>>>(cb,lng,lnb,mb,out);
    loss_write<<<1,1>>>(out,(long)out_size);
}